// round 1
// baseline (speedup 1.0000x reference)
#include <cuda_runtime.h>
#include <cstdint>
#include <cstddef>

// Problem constants (fixed by the benchmark shapes)
#define N_QUERY 32768   // 1024 rays * 32 samples
#define N_LIDAR 8192
#define FDIM    128
#define THREADS 128
#define QPB     256     // queries per block (Q=2 per thread)
#define NBLK    (N_QUERY / QPB)   // 128 blocks

using u64 = unsigned long long;

// ---- packed f32x2 helpers (sm_103a): bitwise-identical to scalar rn ops ----
__device__ __forceinline__ u64 dup2(float x) {
    u64 r; asm("mov.b64 %0, {%1, %1};" : "=l"(r) : "f"(x)); return r;
}
__device__ __forceinline__ u64 mul2(u64 a, u64 b) {
    u64 d; asm("mul.rn.f32x2 %0, %1, %2;" : "=l"(d) : "l"(a), "l"(b)); return d;
}
__device__ __forceinline__ u64 fma2(u64 a, u64 b, u64 c) {
    u64 d; asm("fma.rn.f32x2 %0, %1, %2, %3;" : "=l"(d) : "l"(a), "l"(b), "l"(c)); return d;
}
__device__ __forceinline__ u64 add2(u64 a, u64 b) {
    u64 d; asm("add.rn.f32x2 %0, %1, %2;" : "=l"(d) : "l"(a), "l"(b)); return d;
}
__device__ __forceinline__ float2 asf2(u64 v) {
    float2 f; asm("mov.b64 {%0, %1}, %2;" : "=f"(f.x), "=f"(f.y) : "l"(v)); return f;
}

// d2 for a pair of lidar points, replicating the reference rounding:
//   cross = fma(qz,kz, fma(qy,ky, rn(qx*kx)))          (dot accumulation order)
//   d2    = rn( rn(qsq - 2*cross) + ksq )              (fma(cross,-2,qsq) == sub form exactly)
__device__ __forceinline__ u64 pair_d2(u64 kx, u64 ky, u64 kz, u64 ks,
                                       u64 qx, u64 qy, u64 qz, u64 qs, u64 neg2) {
    u64 cross = fma2(qz, kz, fma2(qy, ky, mul2(qx, kx)));
    return add2(fma2(cross, neg2, qs), ks);
}

// Process 8 lidar points for one query: min-tree + rare first-index recovery.
__device__ __forceinline__ void scan8(
    int j,
    ulonglong2 kxa, ulonglong2 kxb,
    ulonglong2 kya, ulonglong2 kyb,
    ulonglong2 kza, ulonglong2 kzb,
    ulonglong2 ksa, ulonglong2 ksb,
    u64 qx, u64 qy, u64 qz, u64 qs, u64 neg2,
    float& best, int& bi)
{
    u64 d0 = pair_d2(kxa.x, kya.x, kza.x, ksa.x, qx, qy, qz, qs, neg2);
    u64 d1 = pair_d2(kxa.y, kya.y, kza.y, ksa.y, qx, qy, qz, qs, neg2);
    u64 d2 = pair_d2(kxb.x, kyb.x, kzb.x, ksb.x, qx, qy, qz, qs, neg2);
    u64 d3 = pair_d2(kxb.y, kyb.y, kzb.y, ksb.y, qx, qy, qz, qs, neg2);
    float2 f0 = asf2(d0), f1 = asf2(d1), f2 = asf2(d2), f3 = asf2(d3);
    float m = fminf(fminf(fminf(f0.x, f0.y), fminf(f1.x, f1.y)),
                    fminf(fminf(f2.x, f2.y), fminf(f3.x, f3.y)));
    if (m < best) {   // rare: expected ~14% of groups per warp (union over lanes)
        best = m;
        int k = 7;
        if (f3.x == m) k = 6;
        if (f2.y == m) k = 5;
        if (f2.x == m) k = 4;
        if (f1.y == m) k = 3;
        if (f1.x == m) k = 2;
        if (f0.y == m) k = 1;
        if (f0.x == m) k = 0;   // descending so FIRST (lowest) index wins ties
        bi = j + k;
    }
}

__global__ void __launch_bounds__(THREADS, 1)
nn_gather_kernel(const float* __restrict__ pts,
                 const float* __restrict__ lidar,
                 const float* __restrict__ features,
                 float* __restrict__ out)
{
    extern __shared__ float sm[];
    float* skx = sm;
    float* sky = sm + N_LIDAR;
    float* skz = sm + 2 * N_LIDAR;
    float* sks = sm + 3 * N_LIDAR;
    __shared__ int sidx[QPB];

    const int tid = threadIdx.x;

    // Cooperative SoA fill of lidar points + ||k||^2 (stepwise rounding (x^2+y^2)+z^2)
    for (int i = tid; i < N_LIDAR; i += THREADS) {
        float kx = lidar[3 * i + 0];
        float ky = lidar[3 * i + 1];
        float kz = lidar[3 * i + 2];
        skx[i] = kx; sky[i] = ky; skz[i] = kz;
        sks[i] = __fadd_rn(__fadd_rn(__fmul_rn(kx, kx), __fmul_rn(ky, ky)),
                           __fmul_rn(kz, kz));
    }
    __syncthreads();

    // Two queries per thread
    const int m0 = blockIdx.x * QPB + tid;
    const int m1 = m0 + THREADS;

    float qx0 = pts[3 * m0 + 0], qy0 = pts[3 * m0 + 1], qz0 = pts[3 * m0 + 2];
    float qx1 = pts[3 * m1 + 0], qy1 = pts[3 * m1 + 1], qz1 = pts[3 * m1 + 2];
    float qs0 = __fadd_rn(__fadd_rn(__fmul_rn(qx0, qx0), __fmul_rn(qy0, qy0)),
                          __fmul_rn(qz0, qz0));
    float qs1 = __fadd_rn(__fadd_rn(__fmul_rn(qx1, qx1), __fmul_rn(qy1, qy1)),
                          __fmul_rn(qz1, qz1));

    const u64 QX0 = dup2(qx0), QY0 = dup2(qy0), QZ0 = dup2(qz0), QS0 = dup2(qs0);
    const u64 QX1 = dup2(qx1), QY1 = dup2(qy1), QZ1 = dup2(qz1), QS1 = dup2(qs1);
    const u64 NEG2 = dup2(-2.0f);

    float best0 = __int_as_float(0x7f800000), best1 = __int_as_float(0x7f800000);
    int bi0 = 0, bi1 = 0;

    #pragma unroll 2
    for (int j = 0; j < N_LIDAR; j += 8) {
        // 8 points of each SoA component: broadcast LDS.128 (conflict-free)
        ulonglong2 kxa = *(const ulonglong2*)(skx + j);
        ulonglong2 kxb = *(const ulonglong2*)(skx + j + 4);
        ulonglong2 kya = *(const ulonglong2*)(sky + j);
        ulonglong2 kyb = *(const ulonglong2*)(sky + j + 4);
        ulonglong2 kza = *(const ulonglong2*)(skz + j);
        ulonglong2 kzb = *(const ulonglong2*)(skz + j + 4);
        ulonglong2 ksa = *(const ulonglong2*)(sks + j);
        ulonglong2 ksb = *(const ulonglong2*)(sks + j + 4);

        scan8(j, kxa, kxb, kya, kyb, kza, kzb, ksa, ksb,
              QX0, QY0, QZ0, QS0, NEG2, best0, bi0);
        scan8(j, kxa, kxb, kya, kyb, kza, kzb, ksa, ksb,
              QX1, QY1, QZ1, QS1, NEG2, best1, bi1);
    }

    sidx[tid] = bi0;
    sidx[tid + THREADS] = bi1;
    __syncthreads();

    // Warp-cooperative coalesced gather: one query row == 32 lanes x float4
    const int lane = tid & 31;
    const int warp = tid >> 5;
    const size_t qbase = (size_t)blockIdx.x * QPB;
    for (int q = warp; q < QPB; q += THREADS / 32) {
        const int src = sidx[q];
        const float4 v = *(const float4*)(features + (size_t)src * FDIM + lane * 4);
        *(float4*)(out + (qbase + q) * FDIM + lane * 4) = v;
    }
}

extern "C" void kernel_launch(void* const* d_in, const int* in_sizes, int n_in,
                              void* d_out, int out_size) {
    const float* pts      = (const float*)d_in[0];  // (1, 1024, 32, 3)
    const float* lidar    = (const float*)d_in[1];  // (1, 8192, 3)
    const float* features = (const float*)d_in[2];  // (1, 8192, 128)
    float* out = (float*)d_out;                     // (1, 1024, 32, 128)

    const int smem_bytes = 4 * N_LIDAR * (int)sizeof(float);  // 128 KB SoA
    cudaFuncSetAttribute(nn_gather_kernel,
                         cudaFuncAttributeMaxDynamicSharedMemorySize, smem_bytes);

    nn_gather_kernel<<<NBLK, THREADS, smem_bytes>>>(pts, lidar, features, out);
}

// round 2
// speedup vs baseline: 1.3065x; 1.3065x over previous
#include <cuda_runtime.h>
#include <cstdint>
#include <cstddef>

// Problem constants (fixed by the benchmark shapes)
#define N_QUERY 32768   // 1024 rays * 32 samples
#define N_LIDAR 8192
#define FDIM    128
#define THREADS 256
#define QPB     256     // queries per block (1 per thread)
#define NBLK    (N_QUERY / QPB)   // 128 blocks
#define TILE    64      // points per guarded best-update

using u64 = unsigned long long;

// ---- packed f32x2 helpers (sm_103a): bitwise-identical to scalar rn ops ----
__device__ __forceinline__ u64 dup2(float x) {
    u64 r; asm("mov.b64 %0, {%1, %1};" : "=l"(r) : "f"(x)); return r;
}
__device__ __forceinline__ u64 mul2(u64 a, u64 b) {
    u64 d; asm("mul.rn.f32x2 %0, %1, %2;" : "=l"(d) : "l"(a), "l"(b)); return d;
}
__device__ __forceinline__ u64 fma2(u64 a, u64 b, u64 c) {
    u64 d; asm("fma.rn.f32x2 %0, %1, %2, %3;" : "=l"(d) : "l"(a), "l"(b), "l"(c)); return d;
}
__device__ __forceinline__ u64 add2(u64 a, u64 b) {
    u64 d; asm("add.rn.f32x2 %0, %1, %2;" : "=l"(d) : "l"(a), "l"(b)); return d;
}
__device__ __forceinline__ float2 asf2(u64 v) {
    float2 f; asm("mov.b64 {%0, %1}, %2;" : "=f"(f.x), "=f"(f.y) : "l"(v)); return f;
}

// d2 for a pair of lidar points, replicating the reference rounding exactly:
//   cross = fma(qz,kz, fma(qy,ky, rn(qx*kx)))          (dot accumulation order)
//   d2    = rn( rn(qsq - 2*cross) + ksq )              (fma(cross,-2,qsq) == sub form exactly)
__device__ __forceinline__ u64 pair_d2(u64 kx, u64 ky, u64 kz, u64 ks,
                                       u64 qx, u64 qy, u64 qz, u64 qs, u64 neg2) {
    u64 cross = fma2(qz, kz, fma2(qy, ky, mul2(qx, kx)));
    return add2(fma2(cross, neg2, qs), ks);
}

// min of one 8-point group (value only, pure FMNMX tree)
__device__ __forceinline__ float group_min8(
    const float* __restrict__ skx, const float* __restrict__ sky,
    const float* __restrict__ skz, const float* __restrict__ sks,
    int j, u64 qx, u64 qy, u64 qz, u64 qs, u64 neg2)
{
    ulonglong2 kxa = *(const ulonglong2*)(skx + j);
    ulonglong2 kxb = *(const ulonglong2*)(skx + j + 4);
    ulonglong2 kya = *(const ulonglong2*)(sky + j);
    ulonglong2 kyb = *(const ulonglong2*)(sky + j + 4);
    ulonglong2 kza = *(const ulonglong2*)(skz + j);
    ulonglong2 kzb = *(const ulonglong2*)(skz + j + 4);
    ulonglong2 ksa = *(const ulonglong2*)(sks + j);
    ulonglong2 ksb = *(const ulonglong2*)(sks + j + 4);

    float2 f0 = asf2(pair_d2(kxa.x, kya.x, kza.x, ksa.x, qx, qy, qz, qs, neg2));
    float2 f1 = asf2(pair_d2(kxa.y, kya.y, kza.y, ksa.y, qx, qy, qz, qs, neg2));
    float2 f2 = asf2(pair_d2(kxb.x, kyb.x, kzb.x, ksb.x, qx, qy, qz, qs, neg2));
    float2 f3 = asf2(pair_d2(kxb.y, kyb.y, kzb.y, ksb.y, qx, qy, qz, qs, neg2));

    return fminf(fminf(fminf(f0.x, f0.y), fminf(f1.x, f1.y)),
                 fminf(fminf(f2.x, f2.y), fminf(f3.x, f3.y)));
}

__global__ void __launch_bounds__(THREADS, 1)
nn_gather_kernel(const float* __restrict__ pts,
                 const float* __restrict__ lidar,
                 const float* __restrict__ features,
                 float* __restrict__ out)
{
    extern __shared__ float sm[];
    float* skx = sm;
    float* sky = sm + N_LIDAR;
    float* skz = sm + 2 * N_LIDAR;
    float* sks = sm + 3 * N_LIDAR;
    __shared__ int sidx[QPB];

    const int tid = threadIdx.x;

    // Cooperative SoA fill of lidar points + ||k||^2 (stepwise rounding (x^2+y^2)+z^2)
    for (int i = tid; i < N_LIDAR; i += THREADS) {
        float kx = lidar[3 * i + 0];
        float ky = lidar[3 * i + 1];
        float kz = lidar[3 * i + 2];
        skx[i] = kx; sky[i] = ky; skz[i] = kz;
        sks[i] = __fadd_rn(__fadd_rn(__fmul_rn(kx, kx), __fmul_rn(ky, ky)),
                           __fmul_rn(kz, kz));
    }
    __syncthreads();

    // One query per thread
    const int m = blockIdx.x * QPB + tid;
    const float qx = pts[3 * m + 0], qy = pts[3 * m + 1], qz = pts[3 * m + 2];
    const float qs = __fadd_rn(__fadd_rn(__fmul_rn(qx, qx), __fmul_rn(qy, qy)),
                               __fmul_rn(qz, qz));

    const u64 QX = dup2(qx), QY = dup2(qy), QZ = dup2(qz), QS = dup2(qs);
    const u64 NEG2 = dup2(-2.0f);

    float best = __int_as_float(0x7f800000);
    int btile = 0;

    // Branch-free 64-point tiles: pure FMNMX min trees; ONE guarded update per tile.
    for (int t = 0; t < N_LIDAR; t += TILE) {
        float gm[8];
        #pragma unroll
        for (int g = 0; g < 8; g++)
            gm[g] = group_min8(skx, sky, skz, sks, t + 8 * g,
                               QX, QY, QZ, QS, NEG2);
        float tm = fminf(fminf(fminf(gm[0], gm[1]), fminf(gm[2], gm[3])),
                         fminf(fminf(gm[4], gm[5]), fminf(gm[6], gm[7])));
        if (tm < best) { best = tm; btile = t; }   // strict < keeps earliest tile on ties
    }

    // Exact first-index recovery inside the winning tile (bit-identical scalar math).
    int bi = btile;
    {
        bool found = false;
        #pragma unroll 4
        for (int i = 0; i < TILE; i++) {
            const int j = btile + i;
            float cross = __fmaf_rn(qz, skz[j],
                          __fmaf_rn(qy, sky[j], __fmul_rn(qx, skx[j])));
            float d2 = __fadd_rn(__fmaf_rn(cross, -2.0f, qs), sks[j]);
            if (!found && d2 == best) { bi = j; found = true; }
        }
    }

    sidx[tid] = bi;
    __syncthreads();

    // Warp-cooperative coalesced gather: one query row == 32 lanes x float4
    const int lane = tid & 31;
    const int warp = tid >> 5;
    const size_t qbase = (size_t)blockIdx.x * QPB;
    for (int q = warp; q < QPB; q += THREADS / 32) {
        const int src = sidx[q];
        const float4 v = *(const float4*)(features + (size_t)src * FDIM + lane * 4);
        *(float4*)(out + (qbase + q) * FDIM + lane * 4) = v;
    }
}

extern "C" void kernel_launch(void* const* d_in, const int* in_sizes, int n_in,
                              void* d_out, int out_size) {
    const float* pts      = (const float*)d_in[0];  // (1, 1024, 32, 3)
    const float* lidar    = (const float*)d_in[1];  // (1, 8192, 3)
    const float* features = (const float*)d_in[2];  // (1, 8192, 128)
    float* out = (float*)d_out;                     // (1, 1024, 32, 128)

    const int smem_bytes = 4 * N_LIDAR * (int)sizeof(float);  // 128 KB SoA
    cudaFuncSetAttribute(nn_gather_kernel,
                         cudaFuncAttributeMaxDynamicSharedMemorySize, smem_bytes);

    nn_gather_kernel<<<NBLK, THREADS, smem_bytes>>>(pts, lidar, features, out);
}